// round 1
// baseline (speedup 1.0000x reference)
#include <cuda_runtime.h>
#include <math.h>

#define BATCH   262144
#define NNODES  1000000
#define DD      100
#define KP      416   // padded K: 100+100+4+100(t_enc)+100(h)=404 -> 416
#define NP      448   // padded N: 400 -> 448
#define NG      400   // real gate width

// -------- device scratch (allocation-free per harness rules) --------
__device__ float g_XC[(size_t)BATCH * KP];   // assembled input rows [BATCH][416]
__device__ float g_G [(size_t)BATCH * NG];   // gate pre-activations [BATCH][400]
__device__ float g_A [(size_t)BATCH * 64];   // relu(h_new @ W1^T + b1)
__device__ float g_WC[(size_t)NP * KP];      // combined weights [448][416]
__device__ float g_bc[NP];                   // combined bias
__device__ float g_stats[128];               // sum[64], sumsq[64]
__device__ float g_W2e[128];                 // folded W2 [64][2]
__device__ float g_be[2];                    // folded bias

// ===================== K0: prep combined weights, zero stats =====================
__global__ __launch_bounds__(256) void prep_kernel(const float* __restrict__ W_ih,
                                                   const float* __restrict__ W_hh,
                                                   const float* __restrict__ b_ih,
                                                   const float* __restrict__ b_hh) {
    int idx = blockIdx.x * 256 + threadIdx.x;
    if (idx < NP * KP) {
        int r = idx / KP, k = idx % KP;
        float v = 0.f;
        if (r < 200) {
            if (k < 304)       v = W_ih[r * 304 + k];
            else if (k < 404)  v = W_hh[r * 100 + (k - 304)];
        } else if (r < 300) {
            if (k < 304)       v = W_ih[r * 304 + k];
        } else if (r < 400) {
            if (k >= 304 && k < 404) v = W_hh[(r - 100) * 100 + (k - 304)];
        }
        g_WC[idx] = v;
    }
    if (idx < NP) {
        float bv = 0.f;
        if (idx < 200)      bv = b_ih[idx] + b_hh[idx];
        else if (idx < 300) bv = b_ih[idx];
        else if (idx < 400) bv = b_hh[idx - 100];
        g_bc[idx] = bv;
    }
    if (idx < 128) g_stats[idx] = 0.f;
}

// ===================== K1: gather + assemble X rows =====================
// one warp per row; 8 rows per 256-thread block
__global__ __launch_bounds__(256) void assemble_kernel(const int*   __restrict__ n_id,
                                                       const float* __restrict__ memory,
                                                       const int*   __restrict__ last_update,
                                                       const int*   __restrict__ store_src,
                                                       const int*   __restrict__ store_dst,
                                                       const int*   __restrict__ store_t,
                                                       const float* __restrict__ store_msg,
                                                       const float* __restrict__ time_w,
                                                       const float* __restrict__ time_b) {
    int w    = threadIdx.x >> 5;
    int lane = threadIdx.x & 31;
    int b = blockIdx.x * 8 + w;
    int n   = n_id[b];
    int src = store_src[n];
    int dst = store_dst[n];
    float dt = (float)(store_t[n] - last_update[n]);
    float*       xr = g_XC + (size_t)b * KP;
    const float* ms = memory + (size_t)src * DD;
    const float* md = memory + (size_t)dst * DD;
    const float* mn = memory + (size_t)n   * DD;
    #pragma unroll
    for (int c = lane; c < KP; c += 32) {
        float v;
        if (c < 100)      v = ms[c];
        else if (c < 200) v = md[c - 100];
        else if (c < 204) v = store_msg[(size_t)n * 4 + (c - 200)];
        else if (c < 304) {
            int j = c - 204;
            // match jax's mul-then-add rounding (no fma) — dt is large
            float arg = __fadd_rn(__fmul_rn(dt, time_w[j]), time_b[j]);
            v = cosf(arg);
        }
        else if (c < 404) v = mn[c - 304];
        else              v = 0.f;
        xr[c] = v;
    }
}

// ===================== K2: big GEMM  G = XC @ WC^T + bc =====================
// BM=128, BN=64, BK=16, 256 threads, 8x4 per thread
__global__ __launch_bounds__(256) void gemm_kernel() {
    __shared__ float As[16][128];
    __shared__ float Bs[16][64];
    const int m0  = blockIdx.x * 128;
    const int n0  = blockIdx.y * 64;
    const int tid = threadIdx.x;
    const int tx  = tid & 15;   // N dir
    const int ty  = tid >> 4;   // M dir

    float acc[8][4];
    #pragma unroll
    for (int i = 0; i < 8; i++)
        #pragma unroll
        for (int j = 0; j < 4; j++) acc[i][j] = 0.f;

    const float* Abase = g_XC + (size_t)m0 * KP;
    const float* Bbase = g_WC + (size_t)n0 * KP;

    for (int k0 = 0; k0 < KP; k0 += 16) {
        // load A tile 128x16 (2 float4 per thread), store k-major
        #pragma unroll
        for (int i = 0; i < 2; i++) {
            int lin = tid + i * 256;
            int row = lin >> 2;
            int kq  = (lin & 3) * 4;
            float4 v = *(const float4*)(Abase + (size_t)row * KP + k0 + kq);
            As[kq + 0][row] = v.x; As[kq + 1][row] = v.y;
            As[kq + 2][row] = v.z; As[kq + 3][row] = v.w;
        }
        // load B tile 64x16 (1 float4 per thread)
        {
            int row = tid >> 2;
            int kq  = (tid & 3) * 4;
            float4 v = *(const float4*)(Bbase + (size_t)row * KP + k0 + kq);
            Bs[kq + 0][row] = v.x; Bs[kq + 1][row] = v.y;
            Bs[kq + 2][row] = v.z; Bs[kq + 3][row] = v.w;
        }
        __syncthreads();
        #pragma unroll
        for (int k = 0; k < 16; k++) {
            float a[8], bb[4];
            #pragma unroll
            for (int i = 0; i < 8; i++) a[i] = As[k][ty * 8 + i];
            #pragma unroll
            for (int j = 0; j < 4; j++) bb[j] = Bs[k][tx * 4 + j];
            #pragma unroll
            for (int i = 0; i < 8; i++)
                #pragma unroll
                for (int j = 0; j < 4; j++)
                    acc[i][j] = fmaf(a[i], bb[j], acc[i][j]);
        }
        __syncthreads();
    }
    #pragma unroll
    for (int i = 0; i < 8; i++) {
        size_t m = (size_t)(m0 + ty * 8 + i);
        float* Crow = g_G + m * NG;
        #pragma unroll
        for (int j = 0; j < 4; j++) {
            int n = n0 + tx * 4 + j;
            if (n < NG) Crow[n] = acc[i][j] + g_bc[n];
        }
    }
}

// ===================== K3: GRU elementwise + W1 + BN stats =====================
// 256 threads = 8 warps; each warp handles 8 rows; 64 rows per block
__global__ __launch_bounds__(256) void gru_kernel(const float* __restrict__ W1,
                                                  const float* __restrict__ b1) {
    __shared__ float W1s[64 * 100];
    __shared__ __align__(16) float hns[8][100];
    __shared__ float sacc[64], qacc[64];
    int tid = threadIdx.x;
    for (int i = tid; i < 6400; i += 256) W1s[i] = W1[i];
    if (tid < 64)       sacc[tid] = 0.f;
    else if (tid < 128) qacc[tid - 64] = 0.f;
    __syncthreads();

    int w = tid >> 5, lane = tid & 31;
    float b1a = b1[lane], b1b = b1[lane + 32];
    float s0 = 0.f, q0 = 0.f, s1 = 0.f, q1 = 0.f;

    for (int t = 0; t < 8; t++) {
        int b = blockIdx.x * 64 + w * 8 + t;
        const float* Gr = g_G  + (size_t)b * NG;
        const float* hr = g_XC + (size_t)b * KP + 304;
        #pragma unroll
        for (int q = 0; q < 4; q++) {
            int d = lane + q * 32;
            if (d < 100) {
                float rr = 1.f / (1.f + __expf(-Gr[d]));
                float zz = 1.f / (1.f + __expf(-Gr[100 + d]));
                float nn = tanhf(Gr[200 + d] + rr * Gr[300 + d]);
                hns[w][d] = (1.f - zz) * nn + zz * hr[d];
            }
        }
        __syncwarp();
        float y0 = b1a, y1 = b1b;
        const float4* hv  = (const float4*)hns[w];
        const float4* wv0 = (const float4*)(W1s + lane * 100);
        const float4* wv1 = (const float4*)(W1s + (lane + 32) * 100);
        #pragma unroll
        for (int q = 0; q < 25; q++) {
            float4 h = hv[q], a = wv0[q], c = wv1[q];
            y0 += h.x * a.x + h.y * a.y + h.z * a.z + h.w * a.w;
            y1 += h.x * c.x + h.y * c.y + h.z * c.z + h.w * c.w;
        }
        float a0 = fmaxf(y0, 0.f), a1 = fmaxf(y1, 0.f);
        g_A[(size_t)b * 64 + lane]      = a0;
        g_A[(size_t)b * 64 + lane + 32] = a1;
        s0 += a0; q0 += a0 * a0;
        s1 += a1; q1 += a1 * a1;
        __syncwarp();
    }
    atomicAdd(&sacc[lane],      s0); atomicAdd(&qacc[lane],      q0);
    atomicAdd(&sacc[lane + 32], s1); atomicAdd(&qacc[lane + 32], q1);
    __syncthreads();
    if (tid < 64) {
        atomicAdd(&g_stats[tid],      sacc[tid]);
        atomicAdd(&g_stats[64 + tid], qacc[tid]);
    }
}

// ===================== K4: finalize BN, fold into W2 =====================
__global__ void finalize_kernel(const float* __restrict__ gamma,
                                const float* __restrict__ beta,
                                const float* __restrict__ W2,
                                const float* __restrict__ b2) {
    __shared__ float red0[64], red1[64];
    int j = threadIdx.x;  // 64 threads
    float mu  = g_stats[j]      * (1.f / BATCH);
    float var = g_stats[64 + j] * (1.f / BATCH) - mu * mu;
    float inv = rsqrtf(var + 1e-5f);
    float gsc = gamma[j] * inv;
    float w0 = W2[j], w1 = W2[64 + j];
    g_W2e[2 * j]     = w0 * gsc;
    g_W2e[2 * j + 1] = w1 * gsc;
    float c = beta[j] - mu * gsc;
    red0[j] = c * w0;
    red1[j] = c * w1;
    __syncthreads();
    if (j == 0) { float s = 0.f; for (int i = 0; i < 64; i++) s += red0[i]; g_be[0] = b2[0] + s; }
    if (j == 1) { float s = 0.f; for (int i = 0; i < 64; i++) s += red1[i]; g_be[1] = b2[1] + s; }
}

// ===================== K5: output = A @ W2e + be =====================
__global__ __launch_bounds__(256) void out_kernel(float* __restrict__ out) {
    __shared__ float w2s[128];
    __shared__ float bes[2];
    int tid = threadIdx.x;
    if (tid < 128) w2s[tid] = g_W2e[tid];
    if (tid < 2)   bes[tid] = g_be[tid];
    __syncthreads();
    int b = blockIdx.x * 256 + tid;
    const float4* ar = (const float4*)(g_A + (size_t)b * 64);
    float o0 = bes[0], o1 = bes[1];
    #pragma unroll
    for (int q = 0; q < 16; q++) {
        float4 v = ar[q];
        int j = q * 8;  // index into interleaved w2s (2 per channel)
        o0 += v.x * w2s[j]     + v.y * w2s[j + 2] + v.z * w2s[j + 4] + v.w * w2s[j + 6];
        o1 += v.x * w2s[j + 1] + v.y * w2s[j + 3] + v.z * w2s[j + 5] + v.w * w2s[j + 7];
    }
    ((float2*)out)[b] = make_float2(o0, o1);
}

// ===================== launcher =====================
extern "C" void kernel_launch(void* const* d_in, const int* in_sizes, int n_in,
                              void* d_out, int out_size) {
    const int*   n_id        = (const int*)  d_in[0];
    const float* memory      = (const float*)d_in[1];
    const int*   last_update = (const int*)  d_in[2];
    const int*   store_src   = (const int*)  d_in[3];
    const int*   store_dst   = (const int*)  d_in[4];
    const int*   store_t     = (const int*)  d_in[5];
    const float* store_msg   = (const float*)d_in[6];
    const float* time_w      = (const float*)d_in[7];
    const float* time_b      = (const float*)d_in[8];
    const float* W_ih        = (const float*)d_in[9];
    const float* b_ih        = (const float*)d_in[10];
    const float* W_hh        = (const float*)d_in[11];
    const float* b_hh        = (const float*)d_in[12];
    const float* W1          = (const float*)d_in[13];
    const float* b1          = (const float*)d_in[14];
    const float* gamma       = (const float*)d_in[15];
    const float* beta        = (const float*)d_in[16];
    const float* W2          = (const float*)d_in[17];
    const float* b2          = (const float*)d_in[18];
    float*       out         = (float*)d_out;

    prep_kernel<<<(NP * KP + 255) / 256, 256>>>(W_ih, W_hh, b_ih, b_hh);
    assemble_kernel<<<BATCH / 8, 256>>>(n_id, memory, last_update, store_src,
                                        store_dst, store_t, store_msg, time_w, time_b);
    gemm_kernel<<<dim3(BATCH / 128, NP / 64), 256>>>();
    gru_kernel<<<BATCH / 64, 256>>>(W1, b1);
    finalize_kernel<<<1, 64>>>(gamma, beta, W2, b2);
    out_kernel<<<BATCH / 256, 256>>>(out);
}